// round 16
// baseline (speedup 1.0000x reference)
#include <cuda_runtime.h>
#include <cstdint>

// Problem dims
#define BB 2
#define TT 1024
#define DD 768
#define HH 12
#define HSZ 64
#define EE 8
#define DFF 3072
#define NN 2048
#define NPAD 2560                     // NN + EE*64 (64-aligned expert segments)

// GEMM tiling: block 64x64, warp 16x32, 3-stage pipeline
#define AS_STRIDE 36                  // 36j mod 32 = 4j -> LDSM rows conflict-free
#define BS_STRIDE 72                  // 72 mod 32 = 8 -> bank 8t+g distinct
#define AS_BUF (64 * AS_STRIDE)       // 2304 floats
#define BS_BUF (32 * BS_STRIDE)       // 2304 floats
#define B_BASE3 (3 * AS_BUF)
#define SMEM_G_FLOATS (3 * (AS_BUF + BS_BUF))   // 13824 floats = 55296 B

// Attention smem layout (floats)
#define QS_STR 68
#define KS_STR 68
#define VS_STR 72
#define PS_STR 68
#define AQ 0
#define AK (128 * QS_STR)
#define AV (AK + 2 * 64 * KS_STR)
#define AP (AV + 2 * 64 * VS_STR)
#define ATT_SMEM_FLOATS (AP + 128 * PS_STR)     // 35328 floats = 141312 B

// ---------------- scratch ------------------------------------------------------
__device__ float g_h[NN * DD];
__device__ float g_q[NN * DD];
__device__ float g_k[NN * DD];
__device__ float g_v[NN * DD];
__device__ float g_att[NN * DD];
__device__ float g_h2[NN * DD];
__device__ float g_hid[NPAD * DFF];
__device__ int   g_sel[NN];
__device__ int   g_cnt[EE];
__device__ int   g_cur[EE];
__device__ int   g_off[EE + 1];
__device__ int   g_perm[NPAD];

// ---------------- helpers ------------------------------------------------------
__device__ __forceinline__ void cpa16(unsigned s, const float* g) {
    asm volatile("cp.async.ca.shared.global [%0], [%1], 16;\n" :: "r"(s), "l"(g));
}
__device__ __forceinline__ void cp_commit() { asm volatile("cp.async.commit_group;\n"); }
__device__ __forceinline__ void cp_wait1() { asm volatile("cp.async.wait_group 1;\n"); }
__device__ __forceinline__ void cp_wait0() { asm volatile("cp.async.wait_group 0;\n"); }

__device__ __forceinline__ unsigned cvt_tf32(float v) {
    unsigned r;
    asm("cvt.rna.tf32.f32 %0, %1;" : "=r"(r) : "f"(v));
    return r;
}
__device__ __forceinline__ float tf32f(float v) { return __uint_as_float(cvt_tf32(v)); }

__device__ __forceinline__ void ldsm4(unsigned& r0, unsigned& r1, unsigned& r2, unsigned& r3,
                                      unsigned addr) {
    asm volatile("ldmatrix.sync.aligned.m8n8.x4.shared.b16 {%0,%1,%2,%3}, [%4];"
        : "=r"(r0), "=r"(r1), "=r"(r2), "=r"(r3) : "r"(addr));
}

__device__ __forceinline__ void mma8(float* c, const unsigned* a, const unsigned* b) {
    asm volatile(
        "mma.sync.aligned.m16n8k8.row.col.f32.tf32.tf32.f32 "
        "{%0,%1,%2,%3},{%4,%5,%6,%7},{%8,%9},{%0,%1,%2,%3};\n"
        : "+f"(c[0]), "+f"(c[1]), "+f"(c[2]), "+f"(c[3])
        : "r"(a[0]), "r"(a[1]), "r"(a[2]), "r"(a[3]), "r"(b[0]), "r"(b[1]));
}

// A-fragment lane address offset for LDSM x4
__device__ __forceinline__ unsigned afrag_lane_off(int lane, int stride_f) {
    int row_l = (lane & 7) + ((lane >> 3) & 1) * 8;
    int col_l = (lane >> 4) * 4;
    return (unsigned)((row_l * stride_f + col_l) * 4);
}
// B-fragment (row-major [n][k] smem) lane offset
__device__ __forceinline__ unsigned bfrag_lane_off(int lane, int stride_f) {
    int row_l = (lane & 7) + (lane >> 4) * 8;
    int col_l = ((lane >> 3) & 1) * 4;
    return (unsigned)((row_l * stride_f + col_l) * 4);
}

// one 32-wide K chunk: warp tile 16x32 (4 nt). A via LDSM (optional rna cvt),
// B (weights, [k][n] smem) scalar + rna cvt.
template<bool CVTA>
__device__ __forceinline__ void mma_chunk(unsigned aAddr, const float* __restrict__ sB,
                                          float acc[4][4], int g, int t, int mw, int nw) {
#pragma unroll
    for (int ks = 0; ks < 4; ks++) {
        int k8 = ks * 8;
        unsigned a[4], b[4][2];
        ldsm4(a[0], a[1], a[2], a[3], aAddr + (unsigned)((mw * AS_STRIDE + k8) * 4));
        if (CVTA) {
            a[0] = cvt_tf32(__uint_as_float(a[0]));
            a[1] = cvt_tf32(__uint_as_float(a[1]));
            a[2] = cvt_tf32(__uint_as_float(a[2]));
            a[3] = cvt_tf32(__uint_as_float(a[3]));
        }
#pragma unroll
        for (int nt = 0; nt < 4; nt++) {
            int cn = nw + nt * 8 + g;
            b[nt][0] = cvt_tf32(sB[(k8 + t) * BS_STRIDE + cn]);
            b[nt][1] = cvt_tf32(sB[(k8 + t + 4) * BS_STRIDE + cn]);
        }
#pragma unroll
        for (int nt = 0; nt < 4; nt++)
            mma8(acc[nt], a, b[nt]);
    }
}

// ---------------- LayerNorm ----------------------------------------------------
__global__ void ln_kernel(const float* __restrict__ x, const float* __restrict__ gw,
                          const float* __restrict__ gb, int which) {
    float* out = which ? g_h2 : g_h;
    int row = blockIdx.x, tid = threadIdx.x;
    const float* xp = x + (size_t)row * DD;
    float v0 = xp[tid], v1 = xp[tid + 256], v2 = xp[tid + 512];
    float s = v0 + v1 + v2;
    float s2 = v0 * v0 + v1 * v1 + v2 * v2;
#pragma unroll
    for (int o = 16; o; o >>= 1) {
        s  += __shfl_xor_sync(0xffffffffu, s, o);
        s2 += __shfl_xor_sync(0xffffffffu, s2, o);
    }
    __shared__ float r1[8], r2[8];
    if ((tid & 31) == 0) { r1[tid >> 5] = s; r2[tid >> 5] = s2; }
    __syncthreads();
    s = 0.f; s2 = 0.f;
#pragma unroll
    for (int i = 0; i < 8; i++) { s += r1[i]; s2 += r2[i]; }
    float mu = s * (1.f / DD);
    float var = s2 * (1.f / DD) - mu * mu;
    float rs = rsqrtf(var + 1e-5f);
    float* op = out + (size_t)row * DD;
    float o0 = (v0 - mu) * rs * gw[tid]       + gb[tid];
    float o1 = (v1 - mu) * rs * gw[tid + 256] + gb[tid + 256];
    float o2 = (v2 - mu) * rs * gw[tid + 512] + gb[tid + 512];
    if (which == 0) { o0 = tf32f(o0); o1 = tf32f(o1); o2 = tf32f(o2); }
    op[tid] = o0; op[tid + 256] = o1; op[tid + 512] = o2;
}

// ---------------- QKV gemm -----------------------------------------------------
// grid (32, 36): y/12 -> matrix, y%12 -> head (64-wide ntile).
__global__ __launch_bounds__(256, 3) void qkv_tc(
    const float* __restrict__ Wq, const float* __restrict__ Wk, const float* __restrict__ Wv) {
    extern __shared__ float sm[];
    int tid = threadIdx.x, lane = tid & 31, warp = tid >> 5;
    int g = lane >> 2, t = lane & 3;
    int mw = (warp >> 1) * 16, nw = (warp & 1) * 32;
    int m0 = blockIdx.x * 64;
    int y = blockIdx.y;
    int mat = y / 12, h = y % 12;
    const float* W = (mat == 0) ? Wq : (mat == 1 ? Wk : Wv);
    float* dst = (mat == 0) ? g_q : (mat == 1 ? g_k : g_v);
    const float* wb = W + (size_t)h * DD * HSZ;

    unsigned sbase = (unsigned)__cvta_generic_to_shared(sm);
    unsigned aLane = sbase + afrag_lane_off(lane, AS_STRIDE);
    const float* arow[2]; unsigned asmo[2];
    const float* brow[2]; unsigned bsmo[2];
#pragma unroll
    for (int i = 0; i < 2; i++) {
        int f = tid + i * 256;
        int r = f >> 3, kq = (f & 7) * 4;
        arow[i] = g_h + (size_t)(m0 + r) * DD + kq;
        asmo[i] = sbase + (r * AS_STRIDE + kq) * 4;
        int kk = f >> 4, nq = (f & 15) * 4;
        brow[i] = wb + (size_t)kk * HSZ + nq;
        bsmo[i] = sbase + (B_BASE3 + kk * BS_STRIDE + nq) * 4;
    }
    float acc[4][4] = {};
    const int NC = DD / 32;  // 24
#pragma unroll
    for (int p = 0; p < 2; p++) {
        int k0 = p * 32;
#pragma unroll
        for (int i = 0; i < 2; i++) cpa16(asmo[i] + p * AS_BUF * 4, arow[i] + k0);
#pragma unroll
        for (int i = 0; i < 2; i++) cpa16(bsmo[i] + p * BS_BUF * 4, brow[i] + k0 * HSZ);
        cp_commit();
    }
#pragma unroll 1
    for (int c = 0; c < NC; c++) {
        if (c + 1 < NC) cp_wait1(); else cp_wait0();
        __syncthreads();
        int buf = c % 3;
        mma_chunk<false>(aLane + buf * AS_BUF * 4, sm + B_BASE3 + buf * BS_BUF, acc, g, t, mw, nw);
        if (c + 2 < NC) {
            int k0 = (c + 2) * 32, nb = (c + 2) % 3;
#pragma unroll
            for (int i = 0; i < 2; i++) cpa16(asmo[i] + nb * AS_BUF * 4, arow[i] + k0);
#pragma unroll
            for (int i = 0; i < 2; i++) cpa16(bsmo[i] + nb * BS_BUF * 4, brow[i] + k0 * HSZ);
            cp_commit();
        }
    }
#pragma unroll
    for (int nt = 0; nt < 4; nt++) {
        int col = nw + nt * 8 + 2 * t;     // 0..63 within head
#pragma unroll
        for (int half = 0; half < 2; half++) {
            int m = m0 + mw + g + half * 8;
            int b_ = m >> 10, t_ = m & 1023;
            float2 v = make_float2(tf32f(acc[nt][half * 2]),
                                   tf32f(acc[nt][half * 2 + 1]));
            *(float2*)(dst + (((size_t)(b_ * HH + h) * TT + t_) << 6) + col) = v;
        }
    }
}

// ---------------- tensor-core flash attention ---------------------------------
__global__ __launch_bounds__(256) void attn_tc() {
    extern __shared__ float sm[];
    int tid = threadIdx.x, lane = tid & 31, w = tid >> 5;
    int g = lane >> 2, t = lane & 3;
    int qt = (int)gridDim.x - 1 - (int)blockIdx.x;
    int h = blockIdx.y, b = blockIdx.z;
    int m0 = qt * 128;
    const float scale = rsqrtf((float)DD);
    const float* qbase = g_q + ((size_t)(b * HH + h) * TT + m0) * HSZ;
    const float* kbase = g_k + (size_t)(b * HH + h) * TT * HSZ;
    const float* vbase = g_v + (size_t)(b * HH + h) * TT * HSZ;
    unsigned sbase = (unsigned)__cvta_generic_to_shared(sm);
    unsigned qLane = sbase + AQ * 4 + afrag_lane_off(lane, QS_STR);
    unsigned pLane = sbase + AP * 4 + afrag_lane_off(lane, PS_STR);
    unsigned kLane = sbase + AK * 4 + bfrag_lane_off(lane, KS_STR);

    int ntiles = 2 * (qt + 1);
    int r_ = tid >> 4, c_ = (tid & 15) * 4;
    {
#pragma unroll
        for (int i = 0; i < 4; i++) {
            int rr = r_ + i * 16;
            cpa16(sbase + (AK + rr * KS_STR + c_) * 4, kbase + rr * HSZ + c_);
            cpa16(sbase + (AV + rr * VS_STR + c_) * 4, vbase + rr * HSZ + c_);
        }
        cp_commit();
    }
#pragma unroll
    for (int i = 0; i < 8; i++) {
        int f = tid + i * 256;
        int rr = f >> 4, cc = (f & 15) * 4;
        float4 v = *(const float4*)(qbase + (size_t)rr * HSZ + cc);
        v.x = tf32f(v.x * scale); v.y = tf32f(v.y * scale);
        v.z = tf32f(v.z * scale); v.w = tf32f(v.w * scale);
        *(float4*)&sm[AQ + rr * QS_STR + cc] = v;
    }

    int mw = w * 16;
    int qrow0 = m0 + mw + g, qrow1 = qrow0 + 8;
    float m0s = -1e30f, m1s = -1e30f, l0s = 0.f, l1s = 0.f;
    float acc_o[8][4] = {};

#pragma unroll 1
    for (int kt = 0; kt < ntiles; kt++) {
        cp_wait0();
        __syncthreads();
        int buf = kt & 1;
        if (kt + 1 < ntiles) {
            const float* kp = kbase + (size_t)(kt + 1) * 64 * HSZ;
            const float* vp = vbase + (size_t)(kt + 1) * 64 * HSZ;
            int ob = buf ^ 1;
#pragma unroll
            for (int i = 0; i < 4; i++) {
                int rr = r_ + i * 16;
                cpa16(sbase + (AK + ob * 64 * KS_STR + rr * KS_STR + c_) * 4, kp + rr * HSZ + c_);
                cpa16(sbase + (AV + ob * 64 * VS_STR + rr * VS_STR + c_) * 4, vp + rr * HSZ + c_);
            }
            cp_commit();
        }
        const float* vs_ = sm + AV + buf * 64 * VS_STR;
        unsigned kBufLane = kLane + (unsigned)(buf * 64 * KS_STR * 4);

        float s_acc[8][4];
#pragma unroll
        for (int nt = 0; nt < 8; nt++) { s_acc[nt][0] = s_acc[nt][1] = s_acc[nt][2] = s_acc[nt][3] = 0.f; }
#pragma unroll
        for (int k8i = 0; k8i < 8; k8i++) {
            int k8 = k8i * 8;
            unsigned a[4];
            ldsm4(a[0], a[1], a[2], a[3], qLane + (unsigned)((mw * QS_STR + k8) * 4));
#pragma unroll
            for (int p = 0; p < 4; p++) {
                unsigned b0, b1, b2, b3;
                ldsm4(b0, b1, b2, b3, kBufLane + (unsigned)((p * 16 * KS_STR + k8) * 4));
                unsigned bb0[2] = {b0, b1}, bb1[2] = {b2, b3};
                mma8(s_acc[2 * p], a, bb0);
                mma8(s_acc[2 * p + 1], a, bb1);
            }
        }
        int k0 = kt * 64;
        if (kt >= 2 * qt) {
#pragma unroll
            for (int nt = 0; nt < 8; nt++) {
                int c0 = k0 + nt * 8 + 2 * t, c1 = c0 + 1;
                if (c0 > qrow0) s_acc[nt][0] = -1e30f;
                if (c1 > qrow0) s_acc[nt][1] = -1e30f;
                if (c0 > qrow1) s_acc[nt][2] = -1e30f;
                if (c1 > qrow1) s_acc[nt][3] = -1e30f;
            }
        }
        float mt0 = m0s, mt1 = m1s;
#pragma unroll
        for (int nt = 0; nt < 8; nt++) {
            mt0 = fmaxf(mt0, fmaxf(s_acc[nt][0], s_acc[nt][1]));
            mt1 = fmaxf(mt1, fmaxf(s_acc[nt][2], s_acc[nt][3]));
        }
        mt0 = fmaxf(mt0, __shfl_xor_sync(0xffffffffu, mt0, 1));
        mt0 = fmaxf(mt0, __shfl_xor_sync(0xffffffffu, mt0, 2));
        mt1 = fmaxf(mt1, __shfl_xor_sync(0xffffffffu, mt1, 1));
        mt1 = fmaxf(mt1, __shfl_xor_sync(0xffffffffu, mt1, 2));
        float r0 = __expf(m0s - mt0), r1 = __expf(m1s - mt1);
        m0s = mt0; m1s = mt1;
        float ls0 = 0.f, ls1 = 0.f;
#pragma unroll
        for (int nt = 0; nt < 8; nt++) {
            float p0 = __expf(s_acc[nt][0] - mt0);
            float p1 = __expf(s_acc[nt][1] - mt0);
            float p2 = __expf(s_acc[nt][2] - mt1);
            float p3 = __expf(s_acc[nt][3] - mt1);
            ls0 += p0 + p1; ls1 += p2 + p3;
            int cc = nt * 8 + 2 * t;
            *(float2*)&sm[AP + (mw + g) * PS_STR + cc]     = make_float2(tf32f(p0), tf32f(p1));
            *(float2*)&sm[AP + (mw + g + 8) * PS_STR + cc] = make_float2(tf32f(p2), tf32f(p3));
        }
        ls0 += __shfl_xor_sync(0xffffffffu, ls0, 1);
        ls0 += __shfl_xor_sync(0xffffffffu, ls0, 2);
        ls1 += __shfl_xor_sync(0xffffffffu, ls1, 1);
        ls1 += __shfl_xor_sync(0xffffffffu, ls1, 2);
        l0s = l0s * r0 + ls0;
        l1s = l1s * r1 + ls1;
#pragma unroll
        for (int nt = 0; nt < 8; nt++) {
            acc_o[nt][0] *= r0; acc_o[nt][1] *= r0;
            acc_o[nt][2] *= r1; acc_o[nt][3] *= r1;
        }
        __syncwarp();

#pragma unroll
        for (int k8i = 0; k8i < 8; k8i++) {
            int k8 = k8i * 8;
            unsigned a[4];
            ldsm4(a[0], a[1], a[2], a[3], pLane + (unsigned)((mw * PS_STR + k8) * 4));
#pragma unroll
            for (int nt = 0; nt < 8; nt++) {
                unsigned bf[2];
                bf[0] = __float_as_uint(vs_[(k8 + t) * VS_STR + nt * 8 + g]);
                bf[1] = __float_as_uint(vs_[(k8 + t + 4) * VS_STR + nt * 8 + g]);
                mma8(acc_o[nt], a, bf);
            }
        }
        __syncwarp();
    }
    float inv0 = 1.f / l0s, inv1 = 1.f / l1s;
    float* o0 = g_att + ((size_t)(b * TT) + qrow0) * DD + h * HSZ;
    float* o1 = g_att + ((size_t)(b * TT) + qrow1) * DD + h * HSZ;
#pragma unroll
    for (int nt = 0; nt < 8; nt++) {
        int cc = nt * 8 + 2 * t;
        *(float2*)(o0 + cc) = make_float2(tf32f(acc_o[nt][0] * inv0), tf32f(acc_o[nt][1] * inv0));
        *(float2*)(o1 + cc) = make_float2(tf32f(acc_o[nt][2] * inv1), tf32f(acc_o[nt][3] * inv1));
    }
}

// ---------------- output projection + residual ---------------------------------
// grid (32, 12)
__global__ __launch_bounds__(256, 3) void proj_tc(
    const float* __restrict__ Wp, const float* __restrict__ bp,
    const float* __restrict__ x, float* __restrict__ out) {
    extern __shared__ float sm[];
    int tid = threadIdx.x, lane = tid & 31, warp = tid >> 5;
    int g = lane >> 2, t = lane & 3;
    int mw = (warp >> 1) * 16, nw = (warp & 1) * 32;
    int m0 = blockIdx.x * 64;
    int n0 = blockIdx.y * 64;

    unsigned sbase = (unsigned)__cvta_generic_to_shared(sm);
    unsigned aLane = sbase + afrag_lane_off(lane, AS_STRIDE);
    const float* arow[2]; unsigned asmo[2];
    const float* brow[2]; unsigned bsmo[2];
#pragma unroll
    for (int i = 0; i < 2; i++) {
        int f = tid + i * 256;
        int r = f >> 3, kq = (f & 7) * 4;
        arow[i] = g_att + (size_t)(m0 + r) * DD + kq;
        asmo[i] = sbase + (r * AS_STRIDE + kq) * 4;
        int kk = f >> 4, nq = (f & 15) * 4;
        brow[i] = Wp + (size_t)kk * DD + n0 + nq;
        bsmo[i] = sbase + (B_BASE3 + kk * BS_STRIDE + nq) * 4;
    }
    float acc[4][4] = {};
    const int NC = DD / 32;
#pragma unroll
    for (int p = 0; p < 2; p++) {
        int k0 = p * 32;
#pragma unroll
        for (int i = 0; i < 2; i++) cpa16(asmo[i] + p * AS_BUF * 4, arow[i] + k0);
#pragma unroll
        for (int i = 0; i < 2; i++) cpa16(bsmo[i] + p * BS_BUF * 4, brow[i] + (size_t)k0 * DD);
        cp_commit();
    }
#pragma unroll 1
    for (int c = 0; c < NC; c++) {
        if (c + 1 < NC) cp_wait1(); else cp_wait0();
        __syncthreads();
        int buf = c % 3;
        mma_chunk<false>(aLane + buf * AS_BUF * 4, sm + B_BASE3 + buf * BS_BUF, acc, g, t, mw, nw);
        if (c + 2 < NC) {
            int k0 = (c + 2) * 32, nb = (c + 2) % 3;
#pragma unroll
            for (int i = 0; i < 2; i++) cpa16(asmo[i] + nb * AS_BUF * 4, arow[i] + k0);
#pragma unroll
            for (int i = 0; i < 2; i++) cpa16(bsmo[i] + nb * BS_BUF * 4, brow[i] + (size_t)k0 * DD);
            cp_commit();
        }
    }
#pragma unroll
    for (int nt = 0; nt < 4; nt++) {
        int col = n0 + nw + nt * 8 + 2 * t;
#pragma unroll
        for (int half = 0; half < 2; half++) {
            int m = m0 + mw + g + half * 8;
            size_t idx = (size_t)m * DD + col;
            out[idx]     = acc[nt][half * 2]     + bp[col]     + x[idx];
            out[idx + 1] = acc[nt][half * 2 + 1] + bp[col + 1] + x[idx + 1];
        }
    }
}

// ---------------- MoE gate + routing -------------------------------------------
__global__ void moe_zero() { int t = threadIdx.x; if (t < EE) { g_cnt[t] = 0; g_cur[t] = 0; } }

__global__ void gate_kernel(const float* __restrict__ Wg) {
    int gtid = blockIdx.x * blockDim.x + threadIdx.x;
    int warp = gtid >> 5, lane = gtid & 31;
    if (warp >= NN) return;
    const float* hp = g_h2 + (size_t)warp * DD;
    float best = -1e30f; int bi = 0;
    for (int e = 0; e < EE; e++) {
        float s = 0.f;
        for (int i = lane; i < DD; i += 32) s += hp[i] * Wg[i * EE + e];
#pragma unroll
        for (int o = 16; o; o >>= 1) s += __shfl_xor_sync(0xffffffffu, s, o);
        if (s > best) { best = s; bi = e; }
    }
    if (lane == 0) { g_sel[warp] = bi; atomicAdd(&g_cnt[bi], 1); }
}

__global__ void moe_scan() {
    if (threadIdx.x == 0) {
        int o = 0;
        for (int e = 0; e < EE; e++) { g_off[e] = o; o += ((g_cnt[e] + 63) >> 6) << 6; }
        g_off[EE] = o;
    }
}
__global__ void moe_scatter() {
    int n = blockIdx.x * 256 + threadIdx.x;
    if (n < NN) {
        int e = g_sel[n];
        int p = atomicAdd(&g_cur[e], 1);
        g_perm[g_off[e] + p] = n;
    }
}

// ---------------- expert FFN1 ---------------------------------------------------
// grid (40, 48)
__global__ __launch_bounds__(256, 3) void ffn1_tc(const float* __restrict__ W1,
                                                  const float* __restrict__ b1) {
    int row0 = blockIdx.x * 64;
    if (row0 >= g_off[EE]) return;
    int e = 0;
#pragma unroll
    for (int i = 1; i < EE; i++) if (row0 >= g_off[i]) e = i;
    int valid = g_cnt[e] - (row0 - g_off[e]);
    if (valid > 64) valid = 64;
    extern __shared__ float sm[];
    __shared__ int toks[64];
    int tid = threadIdx.x, lane = tid & 31, warp = tid >> 5;
    int g = lane >> 2, t = lane & 3;
    int mw = (warp >> 1) * 16, nw = (warp & 1) * 32;
    if (tid < 64) toks[tid] = (tid < valid) ? g_perm[row0 + tid] : g_perm[row0];
    __syncthreads();
    int n0 = blockIdx.y * 64;
    const float* wb = W1 + (size_t)e * DD * DFF;

    unsigned sbase = (unsigned)__cvta_generic_to_shared(sm);
    unsigned aLane = sbase + afrag_lane_off(lane, AS_STRIDE);
    const float* arow[2]; unsigned asmo[2];
    const float* brow[2]; unsigned bsmo[2];
#pragma unroll
    for (int i = 0; i < 2; i++) {
        int f = tid + i * 256;
        int r = f >> 3, kq = (f & 7) * 4;
        arow[i] = g_h2 + (size_t)toks[r] * DD + kq;
        asmo[i] = sbase + (r * AS_STRIDE + kq) * 4;
        int kk = f >> 4, nq = (f & 15) * 4;
        brow[i] = wb + (size_t)kk * DFF + n0 + nq;
        bsmo[i] = sbase + (B_BASE3 + kk * BS_STRIDE + nq) * 4;
    }
    float acc[4][4] = {};
    const int NC = DD / 32;
#pragma unroll
    for (int p = 0; p < 2; p++) {
        int k0 = p * 32;
#pragma unroll
        for (int i = 0; i < 2; i++) cpa16(asmo[i] + p * AS_BUF * 4, arow[i] + k0);
#pragma unroll
        for (int i = 0; i < 2; i++) cpa16(bsmo[i] + p * BS_BUF * 4, brow[i] + (size_t)k0 * DFF);
        cp_commit();
    }
#pragma unroll 1
    for (int c = 0; c < NC; c++) {
        if (c + 1 < NC) cp_wait1(); else cp_wait0();
        __syncthreads();
        int buf = c % 3;
        mma_chunk<true>(aLane + buf * AS_BUF * 4, sm + B_BASE3 + buf * BS_BUF, acc, g, t, mw, nw);
        if (c + 2 < NC) {
            int k0 = (c + 2) * 32, nb = (c + 2) % 3;
#pragma unroll
            for (int i = 0; i < 2; i++) cpa16(asmo[i] + nb * AS_BUF * 4, arow[i] + k0);
#pragma unroll
            for (int i = 0; i < 2; i++) cpa16(bsmo[i] + nb * BS_BUF * 4, brow[i] + (size_t)k0 * DFF);
            cp_commit();
        }
    }
#pragma unroll
    for (int nt = 0; nt < 4; nt++) {
        int col = n0 + nw + nt * 8 + 2 * t;
#pragma unroll
        for (int half = 0; half < 2; half++) {
            int lr = mw + g + half * 8;
            if (lr < valid) {
                float v0 = acc[nt][half * 2]     + b1[(size_t)e * DFF + col];
                float v1 = acc[nt][half * 2 + 1] + b1[(size_t)e * DFF + col + 1];
                float2 v = make_float2(tf32f(v0 > 0.f ? v0 : 0.f),
                                       tf32f(v1 > 0.f ? v1 : 0.f));
                *(float2*)(g_hid + (size_t)(row0 + lr) * DFF + col) = v;
            }
        }
    }
}

// ---------------- expert FFN2 ---------------------------------------------------
// grid (40, 12), K = 3072
__global__ __launch_bounds__(256, 3) void ffn2_tc(const float* __restrict__ W2,
                                                  const float* __restrict__ b2,
                                                  float* __restrict__ out) {
    int row0 = blockIdx.x * 64;
    if (row0 >= g_off[EE]) return;
    int e = 0;
#pragma unroll
    for (int i = 1; i < EE; i++) if (row0 >= g_off[i]) e = i;
    int valid = g_cnt[e] - (row0 - g_off[e]);
    if (valid > 64) valid = 64;
    extern __shared__ float sm[];
    __shared__ int toks[64];
    int tid = threadIdx.x, lane = tid & 31, warp = tid >> 5;
    int g = lane >> 2, t = lane & 3;
    int mw = (warp >> 1) * 16, nw = (warp & 1) * 32;
    if (tid < 64) toks[tid] = (tid < valid) ? g_perm[row0 + tid] : 0;
    __syncthreads();
    int n0 = blockIdx.y * 64;
    const float* wb = W2 + (size_t)e * DFF * DD;

    unsigned sbase = (unsigned)__cvta_generic_to_shared(sm);
    unsigned aLane = sbase + afrag_lane_off(lane, AS_STRIDE);
    const float* arow[2]; unsigned asmo[2];
    const float* brow[2]; unsigned bsmo[2];
#pragma unroll
    for (int i = 0; i < 2; i++) {
        int f = tid + i * 256;
        int r = f >> 3, kq = (f & 7) * 4;
        arow[i] = g_hid + (size_t)(row0 + r) * DFF + kq;
        asmo[i] = sbase + (r * AS_STRIDE + kq) * 4;
        int kk = f >> 4, nq = (f & 15) * 4;
        brow[i] = wb + (size_t)kk * DD + n0 + nq;
        bsmo[i] = sbase + (B_BASE3 + kk * BS_STRIDE + nq) * 4;
    }
    float acc[4][4] = {};
    const int NC = DFF / 32;   // 96
#pragma unroll
    for (int p = 0; p < 2; p++) {
        int k0 = p * 32;
#pragma unroll
        for (int i = 0; i < 2; i++) cpa16(asmo[i] + p * AS_BUF * 4, arow[i] + k0);
#pragma unroll
        for (int i = 0; i < 2; i++) cpa16(bsmo[i] + p * BS_BUF * 4, brow[i] + (size_t)k0 * DD);
        cp_commit();
    }
#pragma unroll 1
    for (int c = 0; c < NC; c++) {
        if (c + 1 < NC) cp_wait1(); else cp_wait0();
        __syncthreads();
        int buf = c % 3;
        mma_chunk<false>(aLane + buf * AS_BUF * 4, sm + B_BASE3 + buf * BS_BUF, acc, g, t, mw, nw);
        if (c + 2 < NC) {
            int k0 = (c + 2) * 32, nb = (c + 2) % 3;
#pragma unroll
            for (int i = 0; i < 2; i++) cpa16(asmo[i] + nb * AS_BUF * 4, arow[i] + k0);
#pragma unroll
            for (int i = 0; i < 2; i++) cpa16(bsmo[i] + nb * BS_BUF * 4, brow[i] + (size_t)k0 * DD);
            cp_commit();
        }
    }
#pragma unroll
    for (int nt = 0; nt < 4; nt++) {
        int col = n0 + nw + nt * 8 + 2 * t;
#pragma unroll
        for (int half = 0; half < 2; half++) {
            int lr = mw + g + half * 8;
            if (lr < valid) {
                int tok = toks[lr];
                size_t idx = (size_t)tok * DD + col;
                out[idx]     += acc[nt][half * 2]     + b2[(size_t)e * DD + col];
                out[idx + 1] += acc[nt][half * 2 + 1] + b2[(size_t)e * DD + col + 1];
            }
        }
    }
}

// ---------------- launch -------------------------------------------------------
extern "C" void kernel_launch(void* const* d_in, const int* in_sizes, int n_in,
                              void* d_out, int out_size) {
    const float* x     = (const float*)d_in[0];
    const float* ln1_g = (const float*)d_in[1];
    const float* ln1_b = (const float*)d_in[2];
    const float* ln2_g = (const float*)d_in[3];
    const float* ln2_b = (const float*)d_in[4];
    const float* Wq    = (const float*)d_in[5];
    const float* Wk    = (const float*)d_in[6];
    const float* Wv    = (const float*)d_in[7];
    const float* Wp    = (const float*)d_in[8];
    const float* bp    = (const float*)d_in[9];
    const float* Wg    = (const float*)d_in[10];
    const float* W1    = (const float*)d_in[11];
    const float* b1    = (const float*)d_in[12];
    const float* W2    = (const float*)d_in[13];
    const float* b2    = (const float*)d_in[14];
    float* out = (float*)d_out;

    const int smem_g = SMEM_G_FLOATS * 4;        // 55296
    const int smem_a = ATT_SMEM_FLOATS * 4;      // 141312
    static bool attr_set = false;
    if (!attr_set) {
        cudaFuncSetAttribute(qkv_tc,  cudaFuncAttributeMaxDynamicSharedMemorySize, smem_g);
        cudaFuncSetAttribute(proj_tc, cudaFuncAttributeMaxDynamicSharedMemorySize, smem_g);
        cudaFuncSetAttribute(ffn1_tc, cudaFuncAttributeMaxDynamicSharedMemorySize, smem_g);
        cudaFuncSetAttribute(ffn2_tc, cudaFuncAttributeMaxDynamicSharedMemorySize, smem_g);
        cudaFuncSetAttribute(attn_tc, cudaFuncAttributeMaxDynamicSharedMemorySize, smem_a);
        attr_set = true;
    }

    ln_kernel<<<NN, 256>>>(x, ln1_g, ln1_b, 0);
    qkv_tc<<<dim3(NN / 64, 36), 256, smem_g>>>(Wq, Wk, Wv);
    attn_tc<<<dim3(TT / 128, HH, BB), 256, smem_a>>>();
    proj_tc<<<dim3(NN / 64, DD / 64), 256, smem_g>>>(Wp, bp, x, out);
    ln_kernel<<<NN, 256>>>(out, ln2_g, ln2_b, 1);
    moe_zero<<<1, 32>>>();
    gate_kernel<<<NN * 32 / 256, 256>>>(Wg);
    moe_scan<<<1, 1>>>();
    moe_scatter<<<NN / 256, 256>>>();
    ffn1_tc<<<dim3(NPAD / 64, DFF / 64), 256, smem_g>>>(W1, b1);
    ffn2_tc<<<dim3(NPAD / 64, DD / 64), 256, smem_g>>>(W2, b2, out);
}

// round 17
// speedup vs baseline: 1.0864x; 1.0864x over previous
#include <cuda_runtime.h>
#include <cstdint>

// Problem dims
#define BB 2
#define TT 1024
#define DD 768
#define HH 12
#define HSZ 64
#define EE 8
#define DFF 3072
#define NN 2048
#define NPAD 3072                     // NN + EE*128 (128-aligned expert segments)

// GEMM tiling: block 128x64, warp 32x32, 2-stage pipeline, 3 CTAs/SM
#define AS_STRIDE 36                  // 36j mod 32 = 4j -> LDSM rows conflict-free
#define BS_STRIDE 72                  // 72 mod 32 = 8 -> bank 8t+g distinct
#define AS_BUF (128 * AS_STRIDE)      // 4608 floats
#define BS_BUF (32 * BS_STRIDE)       // 2304 floats
#define B_BASE2 (2 * AS_BUF)
#define SMEM_G_FLOATS (2 * (AS_BUF + BS_BUF))   // 13824 floats = 55296 B

// Attention smem layout (floats)
#define QS_STR 68
#define KS_STR 68
#define VS_STR 72
#define PS_STR 68
#define AQ 0
#define AK (128 * QS_STR)
#define AV (AK + 2 * 64 * KS_STR)
#define AP (AV + 2 * 64 * VS_STR)
#define ATT_SMEM_FLOATS (AP + 128 * PS_STR)     // 35328 floats = 141312 B

// ---------------- scratch ------------------------------------------------------
__device__ float g_h[NN * DD];
__device__ float g_q[NN * DD];
__device__ float g_k[NN * DD];
__device__ float g_v[NN * DD];
__device__ float g_att[NN * DD];
__device__ float g_h2[NN * DD];
__device__ float g_hid[NPAD * DFF];
__device__ int   g_sel[NN];
__device__ int   g_cnt[EE];
__device__ int   g_cur[EE];
__device__ int   g_off[EE + 1];
__device__ int   g_perm[NPAD];

// ---------------- helpers ------------------------------------------------------
__device__ __forceinline__ void cpa16(unsigned s, const float* g) {
    asm volatile("cp.async.ca.shared.global [%0], [%1], 16;\n" :: "r"(s), "l"(g));
}
__device__ __forceinline__ void cp_commit() { asm volatile("cp.async.commit_group;\n"); }
__device__ __forceinline__ void cp_wait0() { asm volatile("cp.async.wait_group 0;\n"); }

__device__ __forceinline__ unsigned cvt_tf32(float v) {
    unsigned r;
    asm("cvt.rna.tf32.f32 %0, %1;" : "=r"(r) : "f"(v));
    return r;
}
__device__ __forceinline__ float tf32f(float v) { return __uint_as_float(cvt_tf32(v)); }

__device__ __forceinline__ void ldsm4(unsigned& r0, unsigned& r1, unsigned& r2, unsigned& r3,
                                      unsigned addr) {
    asm volatile("ldmatrix.sync.aligned.m8n8.x4.shared.b16 {%0,%1,%2,%3}, [%4];"
        : "=r"(r0), "=r"(r1), "=r"(r2), "=r"(r3) : "r"(addr));
}

__device__ __forceinline__ void mma8(float* c, const unsigned* a, const unsigned* b) {
    asm volatile(
        "mma.sync.aligned.m16n8k8.row.col.f32.tf32.tf32.f32 "
        "{%0,%1,%2,%3},{%4,%5,%6,%7},{%8,%9},{%0,%1,%2,%3};\n"
        : "+f"(c[0]), "+f"(c[1]), "+f"(c[2]), "+f"(c[3])
        : "r"(a[0]), "r"(a[1]), "r"(a[2]), "r"(a[3]), "r"(b[0]), "r"(b[1]));
}

// A-fragment lane address offset for LDSM x4
__device__ __forceinline__ unsigned afrag_lane_off(int lane, int stride_f) {
    int row_l = (lane & 7) + ((lane >> 3) & 1) * 8;
    int col_l = (lane >> 4) * 4;
    return (unsigned)((row_l * stride_f + col_l) * 4);
}
// B-fragment (row-major [n][k] smem) lane offset
__device__ __forceinline__ unsigned bfrag_lane_off(int lane, int stride_f) {
    int row_l = (lane & 7) + (lane >> 4) * 8;
    int col_l = ((lane >> 3) & 1) * 4;
    return (unsigned)((row_l * stride_f + col_l) * 4);
}

// one 32-wide K chunk: warp tile 32x32 (2 mt x 4 nt). A via LDSM (optional rna),
// B (weights, [k][n] smem) scalar + rna cvt.
template<bool CVTA>
__device__ __forceinline__ void mma_chunk(unsigned aAddr, const float* __restrict__ sB,
                                          float acc[2][4][4], int g, int t, int mw, int nw) {
#pragma unroll
    for (int ks = 0; ks < 4; ks++) {
        int k8 = ks * 8;
        unsigned a[2][4], b[4][2];
#pragma unroll
        for (int mt = 0; mt < 2; mt++) {
            unsigned ad = aAddr + (unsigned)(((mw + mt * 16) * AS_STRIDE + k8) * 4);
            ldsm4(a[mt][0], a[mt][1], a[mt][2], a[mt][3], ad);
            if (CVTA) {
                a[mt][0] = cvt_tf32(__uint_as_float(a[mt][0]));
                a[mt][1] = cvt_tf32(__uint_as_float(a[mt][1]));
                a[mt][2] = cvt_tf32(__uint_as_float(a[mt][2]));
                a[mt][3] = cvt_tf32(__uint_as_float(a[mt][3]));
            }
        }
#pragma unroll
        for (int nt = 0; nt < 4; nt++) {
            int cn = nw + nt * 8 + g;
            b[nt][0] = cvt_tf32(sB[(k8 + t) * BS_STRIDE + cn]);
            b[nt][1] = cvt_tf32(sB[(k8 + t + 4) * BS_STRIDE + cn]);
        }
#pragma unroll
        for (int mt = 0; mt < 2; mt++)
#pragma unroll
            for (int nt = 0; nt < 4; nt++)
                mma8(acc[mt][nt], a[mt], b[nt]);
    }
}

// ---------------- LayerNorm ----------------------------------------------------
// which==1 also zeroes the MoE counters (block 0) so moe_zero launch is dropped.
__global__ void ln_kernel(const float* __restrict__ x, const float* __restrict__ gw,
                          const float* __restrict__ gb, int which) {
    float* out = which ? g_h2 : g_h;
    int row = blockIdx.x, tid = threadIdx.x;
    if (which && row == 0 && tid < EE) { g_cnt[tid] = 0; g_cur[tid] = 0; }
    const float* xp = x + (size_t)row * DD;
    float v0 = xp[tid], v1 = xp[tid + 256], v2 = xp[tid + 512];
    float s = v0 + v1 + v2;
    float s2 = v0 * v0 + v1 * v1 + v2 * v2;
#pragma unroll
    for (int o = 16; o; o >>= 1) {
        s  += __shfl_xor_sync(0xffffffffu, s, o);
        s2 += __shfl_xor_sync(0xffffffffu, s2, o);
    }
    __shared__ float r1[8], r2[8];
    if ((tid & 31) == 0) { r1[tid >> 5] = s; r2[tid >> 5] = s2; }
    __syncthreads();
    s = 0.f; s2 = 0.f;
#pragma unroll
    for (int i = 0; i < 8; i++) { s += r1[i]; s2 += r2[i]; }
    float mu = s * (1.f / DD);
    float var = s2 * (1.f / DD) - mu * mu;
    float rs = rsqrtf(var + 1e-5f);
    float* op = out + (size_t)row * DD;
    float o0 = (v0 - mu) * rs * gw[tid]       + gb[tid];
    float o1 = (v1 - mu) * rs * gw[tid + 256] + gb[tid + 256];
    float o2 = (v2 - mu) * rs * gw[tid + 512] + gb[tid + 512];
    if (which == 0) { o0 = tf32f(o0); o1 = tf32f(o1); o2 = tf32f(o2); }
    op[tid] = o0; op[tid + 256] = o1; op[tid + 512] = o2;
}

// ---------------- QKV gemm -----------------------------------------------------
// grid (16, 36): y/12 -> matrix, y%12 -> head (64-wide ntile).
__global__ __launch_bounds__(256, 3) void qkv_tc(
    const float* __restrict__ Wq, const float* __restrict__ Wk, const float* __restrict__ Wv) {
    extern __shared__ float sm[];
    int tid = threadIdx.x, lane = tid & 31, warp = tid >> 5;
    int g = lane >> 2, t = lane & 3;
    int mw = (warp >> 1) * 32, nw = (warp & 1) * 32;
    int m0 = blockIdx.x * 128;
    int y = blockIdx.y;
    int mat = y / 12, h = y % 12;
    const float* W = (mat == 0) ? Wq : (mat == 1 ? Wk : Wv);
    float* dst = (mat == 0) ? g_q : (mat == 1 ? g_k : g_v);
    const float* wb = W + (size_t)h * DD * HSZ;

    unsigned sbase = (unsigned)__cvta_generic_to_shared(sm);
    unsigned aLane = sbase + afrag_lane_off(lane, AS_STRIDE);
    const float* arow[4]; unsigned asmo[4];
    const float* brow[2]; unsigned bsmo[2];
#pragma unroll
    for (int i = 0; i < 4; i++) {
        int f = tid + i * 256;
        int r = f >> 3, kq = (f & 7) * 4;
        arow[i] = g_h + (size_t)(m0 + r) * DD + kq;
        asmo[i] = sbase + (r * AS_STRIDE + kq) * 4;
    }
#pragma unroll
    for (int i = 0; i < 2; i++) {
        int f = tid + i * 256;
        int kk = f >> 4, nq = (f & 15) * 4;
        brow[i] = wb + (size_t)kk * HSZ + nq;
        bsmo[i] = sbase + (B_BASE2 + kk * BS_STRIDE + nq) * 4;
    }
    float acc[2][4][4] = {};
    const int NC = DD / 32;  // 24
    // prologue: chunk 0
#pragma unroll
    for (int i = 0; i < 4; i++) cpa16(asmo[i], arow[i]);
#pragma unroll
    for (int i = 0; i < 2; i++) cpa16(bsmo[i], brow[i]);
    cp_commit();
#pragma unroll 1
    for (int c = 0; c < NC; c++) {
        cp_wait0();
        __syncthreads();
        if (c + 1 < NC) {
            int k0 = (c + 1) * 32, nb = (c + 1) & 1;
#pragma unroll
            for (int i = 0; i < 4; i++) cpa16(asmo[i] + nb * AS_BUF * 4, arow[i] + k0);
#pragma unroll
            for (int i = 0; i < 2; i++) cpa16(bsmo[i] + nb * BS_BUF * 4, brow[i] + k0 * HSZ);
            cp_commit();
        }
        int buf = c & 1;
        mma_chunk<false>(aLane + buf * AS_BUF * 4, sm + B_BASE2 + buf * BS_BUF, acc, g, t, mw, nw);
    }
#pragma unroll
    for (int mt = 0; mt < 2; mt++) {
#pragma unroll
        for (int nt = 0; nt < 4; nt++) {
            int col = nw + nt * 8 + 2 * t;     // 0..63 within head
#pragma unroll
            for (int half = 0; half < 2; half++) {
                int m = m0 + mw + mt * 16 + g + half * 8;
                int b_ = m >> 10, t_ = m & 1023;
                float2 v = make_float2(tf32f(acc[mt][nt][half * 2]),
                                       tf32f(acc[mt][nt][half * 2 + 1]));
                *(float2*)(dst + (((size_t)(b_ * HH + h) * TT + t_) << 6) + col) = v;
            }
        }
    }
}

// ---------------- tensor-core flash attention ---------------------------------
__global__ __launch_bounds__(256) void attn_tc() {
    extern __shared__ float sm[];
    int tid = threadIdx.x, lane = tid & 31, w = tid >> 5;
    int g = lane >> 2, t = lane & 3;
    int qt = (int)gridDim.x - 1 - (int)blockIdx.x;
    int h = blockIdx.y, b = blockIdx.z;
    int m0 = qt * 128;
    const float scale = rsqrtf((float)DD);
    const float* qbase = g_q + ((size_t)(b * HH + h) * TT + m0) * HSZ;
    const float* kbase = g_k + (size_t)(b * HH + h) * TT * HSZ;
    const float* vbase = g_v + (size_t)(b * HH + h) * TT * HSZ;
    unsigned sbase = (unsigned)__cvta_generic_to_shared(sm);
    unsigned qLane = sbase + AQ * 4 + afrag_lane_off(lane, QS_STR);
    unsigned pLane = sbase + AP * 4 + afrag_lane_off(lane, PS_STR);
    unsigned kLane = sbase + AK * 4 + bfrag_lane_off(lane, KS_STR);

    int ntiles = 2 * (qt + 1);
    int r_ = tid >> 4, c_ = (tid & 15) * 4;
    {
#pragma unroll
        for (int i = 0; i < 4; i++) {
            int rr = r_ + i * 16;
            cpa16(sbase + (AK + rr * KS_STR + c_) * 4, kbase + rr * HSZ + c_);
            cpa16(sbase + (AV + rr * VS_STR + c_) * 4, vbase + rr * HSZ + c_);
        }
        cp_commit();
    }
#pragma unroll
    for (int i = 0; i < 8; i++) {
        int f = tid + i * 256;
        int rr = f >> 4, cc = (f & 15) * 4;
        float4 v = *(const float4*)(qbase + (size_t)rr * HSZ + cc);
        v.x = tf32f(v.x * scale); v.y = tf32f(v.y * scale);
        v.z = tf32f(v.z * scale); v.w = tf32f(v.w * scale);
        *(float4*)&sm[AQ + rr * QS_STR + cc] = v;
    }

    int mw = w * 16;
    int qrow0 = m0 + mw + g, qrow1 = qrow0 + 8;
    float m0s = -1e30f, m1s = -1e30f, l0s = 0.f, l1s = 0.f;
    float acc_o[8][4] = {};

#pragma unroll 1
    for (int kt = 0; kt < ntiles; kt++) {
        cp_wait0();
        __syncthreads();
        int buf = kt & 1;
        if (kt + 1 < ntiles) {
            const float* kp = kbase + (size_t)(kt + 1) * 64 * HSZ;
            const float* vp = vbase + (size_t)(kt + 1) * 64 * HSZ;
            int ob = buf ^ 1;
#pragma unroll
            for (int i = 0; i < 4; i++) {
                int rr = r_ + i * 16;
                cpa16(sbase + (AK + ob * 64 * KS_STR + rr * KS_STR + c_) * 4, kp + rr * HSZ + c_);
                cpa16(sbase + (AV + ob * 64 * VS_STR + rr * VS_STR + c_) * 4, vp + rr * HSZ + c_);
            }
            cp_commit();
        }
        const float* vs_ = sm + AV + buf * 64 * VS_STR;
        unsigned kBufLane = kLane + (unsigned)(buf * 64 * KS_STR * 4);

        float s_acc[8][4];
#pragma unroll
        for (int nt = 0; nt < 8; nt++) { s_acc[nt][0] = s_acc[nt][1] = s_acc[nt][2] = s_acc[nt][3] = 0.f; }
#pragma unroll
        for (int k8i = 0; k8i < 8; k8i++) {
            int k8 = k8i * 8;
            unsigned a[4];
            ldsm4(a[0], a[1], a[2], a[3], qLane + (unsigned)((mw * QS_STR + k8) * 4));
#pragma unroll
            for (int p = 0; p < 4; p++) {
                unsigned b0, b1, b2, b3;
                ldsm4(b0, b1, b2, b3, kBufLane + (unsigned)((p * 16 * KS_STR + k8) * 4));
                unsigned bb0[2] = {b0, b1}, bb1[2] = {b2, b3};
                mma8(s_acc[2 * p], a, bb0);
                mma8(s_acc[2 * p + 1], a, bb1);
            }
        }
        int k0 = kt * 64;
        if (kt >= 2 * qt) {
#pragma unroll
            for (int nt = 0; nt < 8; nt++) {
                int c0 = k0 + nt * 8 + 2 * t, c1 = c0 + 1;
                if (c0 > qrow0) s_acc[nt][0] = -1e30f;
                if (c1 > qrow0) s_acc[nt][1] = -1e30f;
                if (c0 > qrow1) s_acc[nt][2] = -1e30f;
                if (c1 > qrow1) s_acc[nt][3] = -1e30f;
            }
        }
        float mt0 = m0s, mt1 = m1s;
#pragma unroll
        for (int nt = 0; nt < 8; nt++) {
            mt0 = fmaxf(mt0, fmaxf(s_acc[nt][0], s_acc[nt][1]));
            mt1 = fmaxf(mt1, fmaxf(s_acc[nt][2], s_acc[nt][3]));
        }
        mt0 = fmaxf(mt0, __shfl_xor_sync(0xffffffffu, mt0, 1));
        mt0 = fmaxf(mt0, __shfl_xor_sync(0xffffffffu, mt0, 2));
        mt1 = fmaxf(mt1, __shfl_xor_sync(0xffffffffu, mt1, 1));
        mt1 = fmaxf(mt1, __shfl_xor_sync(0xffffffffu, mt1, 2));
        float r0 = __expf(m0s - mt0), r1 = __expf(m1s - mt1);
        m0s = mt0; m1s = mt1;
        float ls0 = 0.f, ls1 = 0.f;
#pragma unroll
        for (int nt = 0; nt < 8; nt++) {
            float p0 = __expf(s_acc[nt][0] - mt0);
            float p1 = __expf(s_acc[nt][1] - mt0);
            float p2 = __expf(s_acc[nt][2] - mt1);
            float p3 = __expf(s_acc[nt][3] - mt1);
            ls0 += p0 + p1; ls1 += p2 + p3;
            int cc = nt * 8 + 2 * t;
            *(float2*)&sm[AP + (mw + g) * PS_STR + cc]     = make_float2(tf32f(p0), tf32f(p1));
            *(float2*)&sm[AP + (mw + g + 8) * PS_STR + cc] = make_float2(tf32f(p2), tf32f(p3));
        }
        ls0 += __shfl_xor_sync(0xffffffffu, ls0, 1);
        ls0 += __shfl_xor_sync(0xffffffffu, ls0, 2);
        ls1 += __shfl_xor_sync(0xffffffffu, ls1, 1);
        ls1 += __shfl_xor_sync(0xffffffffu, ls1, 2);
        l0s = l0s * r0 + ls0;
        l1s = l1s * r1 + ls1;
#pragma unroll
        for (int nt = 0; nt < 8; nt++) {
            acc_o[nt][0] *= r0; acc_o[nt][1] *= r0;
            acc_o[nt][2] *= r1; acc_o[nt][3] *= r1;
        }
        __syncwarp();

#pragma unroll
        for (int k8i = 0; k8i < 8; k8i++) {
            int k8 = k8i * 8;
            unsigned a[4];
            ldsm4(a[0], a[1], a[2], a[3], pLane + (unsigned)((mw * PS_STR + k8) * 4));
#pragma unroll
            for (int nt = 0; nt < 8; nt++) {
                unsigned bf[2];
                bf[0] = __float_as_uint(vs_[(k8 + t) * VS_STR + nt * 8 + g]);
                bf[1] = __float_as_uint(vs_[(k8 + t + 4) * VS_STR + nt * 8 + g]);
                mma8(acc_o[nt], a, bf);
            }
        }
        __syncwarp();
    }
    float inv0 = 1.f / l0s, inv1 = 1.f / l1s;
    float* o0 = g_att + ((size_t)(b * TT) + qrow0) * DD + h * HSZ;
    float* o1 = g_att + ((size_t)(b * TT) + qrow1) * DD + h * HSZ;
#pragma unroll
    for (int nt = 0; nt < 8; nt++) {
        int cc = nt * 8 + 2 * t;
        *(float2*)(o0 + cc) = make_float2(tf32f(acc_o[nt][0] * inv0), tf32f(acc_o[nt][1] * inv0));
        *(float2*)(o1 + cc) = make_float2(tf32f(acc_o[nt][2] * inv1), tf32f(acc_o[nt][3] * inv1));
    }
}

// ---------------- output projection + residual ---------------------------------
// grid (16, 12)
__global__ __launch_bounds__(256, 3) void proj_tc(
    const float* __restrict__ Wp, const float* __restrict__ bp,
    const float* __restrict__ x, float* __restrict__ out) {
    extern __shared__ float sm[];
    int tid = threadIdx.x, lane = tid & 31, warp = tid >> 5;
    int g = lane >> 2, t = lane & 3;
    int mw = (warp >> 1) * 32, nw = (warp & 1) * 32;
    int m0 = blockIdx.x * 128;
    int n0 = blockIdx.y * 64;

    unsigned sbase = (unsigned)__cvta_generic_to_shared(sm);
    unsigned aLane = sbase + afrag_lane_off(lane, AS_STRIDE);
    const float* arow[4]; unsigned asmo[4];
    const float* brow[2]; unsigned bsmo[2];
#pragma unroll
    for (int i = 0; i < 4; i++) {
        int f = tid + i * 256;
        int r = f >> 3, kq = (f & 7) * 4;
        arow[i] = g_att + (size_t)(m0 + r) * DD + kq;
        asmo[i] = sbase + (r * AS_STRIDE + kq) * 4;
    }
#pragma unroll
    for (int i = 0; i < 2; i++) {
        int f = tid + i * 256;
        int kk = f >> 4, nq = (f & 15) * 4;
        brow[i] = Wp + (size_t)kk * DD + n0 + nq;
        bsmo[i] = sbase + (B_BASE2 + kk * BS_STRIDE + nq) * 4;
    }
    float acc[2][4][4] = {};
    const int NC = DD / 32;
#pragma unroll
    for (int i = 0; i < 4; i++) cpa16(asmo[i], arow[i]);
#pragma unroll
    for (int i = 0; i < 2; i++) cpa16(bsmo[i], brow[i]);
    cp_commit();
#pragma unroll 1
    for (int c = 0; c < NC; c++) {
        cp_wait0();
        __syncthreads();
        if (c + 1 < NC) {
            int k0 = (c + 1) * 32, nb = (c + 1) & 1;
#pragma unroll
            for (int i = 0; i < 4; i++) cpa16(asmo[i] + nb * AS_BUF * 4, arow[i] + k0);
#pragma unroll
            for (int i = 0; i < 2; i++) cpa16(bsmo[i] + nb * BS_BUF * 4, brow[i] + (size_t)k0 * DD);
            cp_commit();
        }
        int buf = c & 1;
        mma_chunk<false>(aLane + buf * AS_BUF * 4, sm + B_BASE2 + buf * BS_BUF, acc, g, t, mw, nw);
    }
#pragma unroll
    for (int mt = 0; mt < 2; mt++) {
#pragma unroll
        for (int nt = 0; nt < 4; nt++) {
            int col = n0 + nw + nt * 8 + 2 * t;
#pragma unroll
            for (int half = 0; half < 2; half++) {
                int m = m0 + mw + mt * 16 + g + half * 8;
                size_t idx = (size_t)m * DD + col;
                out[idx]     = acc[mt][nt][half * 2]     + bp[col]     + x[idx];
                out[idx + 1] = acc[mt][nt][half * 2 + 1] + bp[col + 1] + x[idx + 1];
            }
        }
    }
}

// ---------------- MoE gate + routing -------------------------------------------
__global__ void gate_kernel(const float* __restrict__ Wg) {
    int gtid = blockIdx.x * blockDim.x + threadIdx.x;
    int warp = gtid >> 5, lane = gtid & 31;
    if (warp >= NN) return;
    const float* hp = g_h2 + (size_t)warp * DD;
    float best = -1e30f; int bi = 0;
    for (int e = 0; e < EE; e++) {
        float s = 0.f;
        for (int i = lane; i < DD; i += 32) s += hp[i] * Wg[i * EE + e];
#pragma unroll
        for (int o = 16; o; o >>= 1) s += __shfl_xor_sync(0xffffffffu, s, o);
        if (s > best) { best = s; bi = e; }
    }
    if (lane == 0) { g_sel[warp] = bi; atomicAdd(&g_cnt[bi], 1); }
}

// scan + scatter fused: single block, 256 threads
__global__ void moe_route() {
    int tid = threadIdx.x;
    if (tid == 0) {
        int o = 0;
        for (int e = 0; e < EE; e++) { g_off[e] = o; o += ((g_cnt[e] + 127) >> 7) << 7; }
        g_off[EE] = o;
    }
    __syncthreads();
    for (int n = tid; n < NN; n += 256) {
        int e = g_sel[n];
        int p = atomicAdd(&g_cur[e], 1);
        g_perm[g_off[e] + p] = n;
    }
}

// ---------------- expert FFN1 ---------------------------------------------------
// grid (24, 48)
__global__ __launch_bounds__(256, 3) void ffn1_tc(const float* __restrict__ W1,
                                                  const float* __restrict__ b1) {
    int row0 = blockIdx.x * 128;
    if (row0 >= g_off[EE]) return;
    int e = 0;
#pragma unroll
    for (int i = 1; i < EE; i++) if (row0 >= g_off[i]) e = i;
    int valid = g_cnt[e] - (row0 - g_off[e]);
    if (valid > 128) valid = 128;
    extern __shared__ float sm[];
    __shared__ int toks[128];
    int tid = threadIdx.x, lane = tid & 31, warp = tid >> 5;
    int g = lane >> 2, t = lane & 3;
    int mw = (warp >> 1) * 32, nw = (warp & 1) * 32;
    if (tid < 128) toks[tid] = (tid < valid) ? g_perm[row0 + tid] : g_perm[row0];
    __syncthreads();
    int n0 = blockIdx.y * 64;
    const float* wb = W1 + (size_t)e * DD * DFF;

    unsigned sbase = (unsigned)__cvta_generic_to_shared(sm);
    unsigned aLane = sbase + afrag_lane_off(lane, AS_STRIDE);
    const float* arow[4]; unsigned asmo[4];
    const float* brow[2]; unsigned bsmo[2];
#pragma unroll
    for (int i = 0; i < 4; i++) {
        int f = tid + i * 256;
        int r = f >> 3, kq = (f & 7) * 4;
        arow[i] = g_h2 + (size_t)toks[r] * DD + kq;
        asmo[i] = sbase + (r * AS_STRIDE + kq) * 4;
    }
#pragma unroll
    for (int i = 0; i < 2; i++) {
        int f = tid + i * 256;
        int kk = f >> 4, nq = (f & 15) * 4;
        brow[i] = wb + (size_t)kk * DFF + n0 + nq;
        bsmo[i] = sbase + (B_BASE2 + kk * BS_STRIDE + nq) * 4;
    }
    float acc[2][4][4] = {};
    const int NC = DD / 32;
#pragma unroll
    for (int i = 0; i < 4; i++) cpa16(asmo[i], arow[i]);
#pragma unroll
    for (int i = 0; i < 2; i++) cpa16(bsmo[i], brow[i]);
    cp_commit();
#pragma unroll 1
    for (int c = 0; c < NC; c++) {
        cp_wait0();
        __syncthreads();
        if (c + 1 < NC) {
            int k0 = (c + 1) * 32, nb = (c + 1) & 1;
#pragma unroll
            for (int i = 0; i < 4; i++) cpa16(asmo[i] + nb * AS_BUF * 4, arow[i] + k0);
#pragma unroll
            for (int i = 0; i < 2; i++) cpa16(bsmo[i] + nb * BS_BUF * 4, brow[i] + (size_t)k0 * DFF);
            cp_commit();
        }
        int buf = c & 1;
        mma_chunk<true>(aLane + buf * AS_BUF * 4, sm + B_BASE2 + buf * BS_BUF, acc, g, t, mw, nw);
    }
#pragma unroll
    for (int mt = 0; mt < 2; mt++) {
#pragma unroll
        for (int nt = 0; nt < 4; nt++) {
            int col = n0 + nw + nt * 8 + 2 * t;
#pragma unroll
            for (int half = 0; half < 2; half++) {
                int lr = mw + mt * 16 + g + half * 8;
                if (lr < valid) {
                    float v0 = acc[mt][nt][half * 2]     + b1[(size_t)e * DFF + col];
                    float v1 = acc[mt][nt][half * 2 + 1] + b1[(size_t)e * DFF + col + 1];
                    float2 v = make_float2(tf32f(v0 > 0.f ? v0 : 0.f),
                                           tf32f(v1 > 0.f ? v1 : 0.f));
                    *(float2*)(g_hid + (size_t)(row0 + lr) * DFF + col) = v;
                }
            }
        }
    }
}

// ---------------- expert FFN2 ---------------------------------------------------
// grid (24, 12), K = 3072
__global__ __launch_bounds__(256, 3) void ffn2_tc(const float* __restrict__ W2,
                                                  const float* __restrict__ b2,
                                                  float* __restrict__ out) {
    int row0 = blockIdx.x * 128;
    if (row0 >= g_off[EE]) return;
    int e = 0;
#pragma unroll
    for (int i = 1; i < EE; i++) if (row0 >= g_off[i]) e = i;
    int valid = g_cnt[e] - (row0 - g_off[e]);
    if (valid > 128) valid = 128;
    extern __shared__ float sm[];
    __shared__ int toks[128];
    int tid = threadIdx.x, lane = tid & 31, warp = tid >> 5;
    int g = lane >> 2, t = lane & 3;
    int mw = (warp >> 1) * 32, nw = (warp & 1) * 32;
    if (tid < 128) toks[tid] = (tid < valid) ? g_perm[row0 + tid] : 0;
    __syncthreads();
    int n0 = blockIdx.y * 64;
    const float* wb = W2 + (size_t)e * DFF * DD;

    unsigned sbase = (unsigned)__cvta_generic_to_shared(sm);
    unsigned aLane = sbase + afrag_lane_off(lane, AS_STRIDE);
    const float* arow[4]; unsigned asmo[4];
    const float* brow[2]; unsigned bsmo[2];
#pragma unroll
    for (int i = 0; i < 4; i++) {
        int f = tid + i * 256;
        int r = f >> 3, kq = (f & 7) * 4;
        arow[i] = g_hid + (size_t)(row0 + r) * DFF + kq;
        asmo[i] = sbase + (r * AS_STRIDE + kq) * 4;
    }
#pragma unroll
    for (int i = 0; i < 2; i++) {
        int f = tid + i * 256;
        int kk = f >> 4, nq = (f & 15) * 4;
        brow[i] = wb + (size_t)kk * DD + n0 + nq;
        bsmo[i] = sbase + (B_BASE2 + kk * BS_STRIDE + nq) * 4;
    }
    float acc[2][4][4] = {};
    const int NC = DFF / 32;   // 96
#pragma unroll
    for (int i = 0; i < 4; i++) cpa16(asmo[i], arow[i]);
#pragma unroll
    for (int i = 0; i < 2; i++) cpa16(bsmo[i], brow[i]);
    cp_commit();
#pragma unroll 1
    for (int c = 0; c < NC; c++) {
        cp_wait0();
        __syncthreads();
        if (c + 1 < NC) {
            int k0 = (c + 1) * 32, nb = (c + 1) & 1;
#pragma unroll
            for (int i = 0; i < 4; i++) cpa16(asmo[i] + nb * AS_BUF * 4, arow[i] + k0);
#pragma unroll
            for (int i = 0; i < 2; i++) cpa16(bsmo[i] + nb * BS_BUF * 4, brow[i] + (size_t)k0 * DD);
            cp_commit();
        }
        int buf = c & 1;
        mma_chunk<false>(aLane + buf * AS_BUF * 4, sm + B_BASE2 + buf * BS_BUF, acc, g, t, mw, nw);
    }
#pragma unroll
    for (int mt = 0; mt < 2; mt++) {
#pragma unroll
        for (int nt = 0; nt < 4; nt++) {
            int col = n0 + nw + nt * 8 + 2 * t;
#pragma unroll
            for (int half = 0; half < 2; half++) {
                int lr = mw + mt * 16 + g + half * 8;
                if (lr < valid) {
                    int tok = toks[lr];
                    size_t idx = (size_t)tok * DD + col;
                    out[idx]     += acc[mt][nt][half * 2]     + b2[(size_t)e * DD + col];
                    out[idx + 1] += acc[mt][nt][half * 2 + 1] + b2[(size_t)e * DD + col + 1];
                }
            }
        }
    }
}

// ---------------- launch -------------------------------------------------------
extern "C" void kernel_launch(void* const* d_in, const int* in_sizes, int n_in,
                              void* d_out, int out_size) {
    const float* x     = (const float*)d_in[0];
    const float* ln1_g = (const float*)d_in[1];
    const float* ln1_b = (const float*)d_in[2];
    const float* ln2_g = (const float*)d_in[3];
    const float* ln2_b = (const float*)d_in[4];
    const float* Wq    = (const float*)d_in[5];
    const float* Wk    = (const float*)d_in[6];
    const float* Wv    = (const float*)d_in[7];
    const float* Wp    = (const float*)d_in[8];
    const float* bp    = (const float*)d_in[9];
    const float* Wg    = (const float*)d_in[10];
    const float* W1    = (const float*)d_in[11];
    const float* b1    = (const float*)d_in[12];
    const float* W2    = (const float*)d_in[13];
    const float* b2    = (const float*)d_in[14];
    float* out = (float*)d_out;

    const int smem_g = SMEM_G_FLOATS * 4;        // 55296
    const int smem_a = ATT_SMEM_FLOATS * 4;      // 141312
    static bool attr_set = false;
    if (!attr_set) {
        cudaFuncSetAttribute(qkv_tc,  cudaFuncAttributeMaxDynamicSharedMemorySize, smem_g);
        cudaFuncSetAttribute(proj_tc, cudaFuncAttributeMaxDynamicSharedMemorySize, smem_g);
        cudaFuncSetAttribute(ffn1_tc, cudaFuncAttributeMaxDynamicSharedMemorySize, smem_g);
        cudaFuncSetAttribute(ffn2_tc, cudaFuncAttributeMaxDynamicSharedMemorySize, smem_g);
        cudaFuncSetAttribute(attn_tc, cudaFuncAttributeMaxDynamicSharedMemorySize, smem_a);
        attr_set = true;
    }

    ln_kernel<<<NN, 256>>>(x, ln1_g, ln1_b, 0);
    qkv_tc<<<dim3(NN / 128, 36), 256, smem_g>>>(Wq, Wk, Wv);
    attn_tc<<<dim3(TT / 128, HH, BB), 256, smem_a>>>();
    proj_tc<<<dim3(NN / 128, DD / 64), 256, smem_g>>>(Wp, bp, x, out);
    ln_kernel<<<NN, 256>>>(out, ln2_g, ln2_b, 1);
    gate_kernel<<<NN * 32 / 256, 256>>>(Wg);
    moe_route<<<1, 256>>>();
    ffn1_tc<<<dim3(NPAD / 128, DFF / 64), 256, smem_g>>>(W1, b1);
    ffn2_tc<<<dim3(NPAD / 128, DD / 64), 256, smem_g>>>(W2, b2, out);
}